// round 2
// baseline (speedup 1.0000x reference)
#include <cuda_runtime.h>
#include <cuda_bf16.h>
#include <cstdint>

#define BATCH 64
#define NANCH 8400
#define NCLS  80
#define MAXOUT 100
#define TPB   512
#define KPT   17          // 512*17 = 8704 >= 8400

__device__ __constant__ float kNegInf = -1e30f;

// Scratch (static __device__ allowed; no runtime allocs)
__device__ float4 g_boxes[BATCH * NANCH];
__device__ float  g_scores[BATCH * NANCH];
__device__ int    g_labels[BATCH * NANCH];
__device__ int    g_sel[BATCH * MAXOUT];

// ---------------------------------------------------------------------------
// Kernel 1: decode. Thread per (batch, anchor). Streams 36 float4s.
// ---------------------------------------------------------------------------
__global__ void decode_kernel(const float* __restrict__ preds,
                              const float* __restrict__ anchors)
{
    int tid = blockIdx.x * blockDim.x + threadIdx.x;   // grid exactly covers B*N
    int n = tid % NANCH;

    const float4* p4 = reinterpret_cast<const float4*>(preds) + (size_t)tid * 36;

    // ---- DFL decode: 4 sides x 16 bins, softmax-expectation ----
    float d[4];
#pragma unroll
    for (int s = 0; s < 4; ++s) {
        float v[16];
#pragma unroll
        for (int q = 0; q < 4; ++q) {
            float4 f = p4[s * 4 + q];
            v[q * 4 + 0] = f.x; v[q * 4 + 1] = f.y;
            v[q * 4 + 2] = f.z; v[q * 4 + 3] = f.w;
        }
        float m = v[0];
#pragma unroll
        for (int i = 1; i < 16; ++i) m = fmaxf(m, v[i]);
        float se = 0.f, ws = 0.f;
#pragma unroll
        for (int i = 0; i < 16; ++i) {
            float e = __expf(v[i] - m);
            se += e;
            ws = fmaf(e, (float)i, ws);
        }
        d[s] = ws / se;
    }

    // ---- class max / argmax (first-max wins, matching jnp.argmax) ----
    float best = -3.402823466e38f;
    int lab = 0;
#pragma unroll
    for (int i = 0; i < 20; ++i) {
        float4 f = p4[16 + i];
        if (f.x > best) { best = f.x; lab = 4 * i + 0; }
        if (f.y > best) { best = f.y; lab = 4 * i + 1; }
        if (f.z > best) { best = f.z; lab = 4 * i + 2; }
        if (f.w > best) { best = f.w; lab = 4 * i + 3; }
    }

    // ---- box construction ----
    float4 a = reinterpret_cast<const float4*>(anchors)[n];
    float hw0 = a.z - a.x;
    float hw1 = a.w - a.y;
    float c0 = (a.x + a.z) * 0.5f;
    float c1 = (a.y + a.w) * 0.5f;
    float bc0 = (d[2] - d[0]) * 0.5f * hw0 + c0;
    float bc1 = (d[3] - d[1]) * 0.5f * hw1 + c1;
    float bh0 = (d[2] + d[0]) * hw0;
    float bh1 = (d[3] + d[1]) * hw1;

    float4 box;
    box.x = bc0 - bh0 * 0.5f;
    box.y = bc1 - bh1 * 0.5f;
    box.z = bc0 + bh0 * 0.5f;
    box.w = bc1 + bh1 * 0.5f;

    g_boxes[tid]  = box;
    g_scores[tid] = (best > 0.3f) ? best : -1e30f;
    g_labels[tid] = lab;
}

// ---------------------------------------------------------------------------
// Kernel 2: greedy NMS, one CTA per image. Boxes+scores register-resident.
// ---------------------------------------------------------------------------
__global__ void __launch_bounds__(TPB, 1) nms_kernel()
{
    const int b = blockIdx.x;
    const int t = threadIdx.x;
    const int warp = t >> 5;
    const int lane = t & 31;

    const float4* gb = g_boxes  + (size_t)b * NANCH;
    const float*  gs = g_scores + (size_t)b * NANCH;

    float4 bx[KPT];
    float  sc[KPT];
    float lv = -3.402823466e38f;
    int   li = 0;

#pragma unroll
    for (int k = 0; k < KPT; ++k) {
        int idx = t + k * TPB;
        if (idx < NANCH) {
            bx[k] = gb[idx];
            sc[k] = gs[idx];
        } else {
            bx[k] = make_float4(0.f, 0.f, 0.f, 0.f);
            sc[k] = -1e30f;
        }
        if (sc[k] > lv) { lv = sc[k]; li = idx; }   // ascending k -> lowest idx on tie
    }

    __shared__ float s_val[16];
    __shared__ int   s_idx[16];
    __shared__ float4 s_box;
    __shared__ float  s_rhs;
    __shared__ int    s_j;
    __shared__ float  s_v;

    for (int it = 0; it < MAXOUT; ++it) {
        // ---- block argmax (tie-break: lowest global index) ----
        float v = lv; int ix = li;
#pragma unroll
        for (int off = 16; off; off >>= 1) {
            float ov = __shfl_down_sync(0xffffffffu, v, off);
            int   oi = __shfl_down_sync(0xffffffffu, ix, off);
            if (ov > v || (ov == v && oi < ix)) { v = ov; ix = oi; }
        }
        if (lane == 0) { s_val[warp] = v; s_idx[warp] = ix; }
        __syncthreads();

        if (warp == 0) {
            float v2 = (lane < 16) ? s_val[lane] : -3.402823466e38f;
            int   i2 = (lane < 16) ? s_idx[lane] : 0x7fffffff;
#pragma unroll
            for (int off = 16; off; off >>= 1) {
                float ov = __shfl_down_sync(0xffffffffu, v2, off);
                int   oi = __shfl_down_sync(0xffffffffu, i2, off);
                if (ov > v2 || (ov == v2 && oi < i2)) { v2 = ov; i2 = oi; }
            }
            if (lane == 0) { s_j = i2; s_v = v2; }
        }
        __syncthreads();

        const int j = s_j;
        const float val = s_v;
        const int ot = j & (TPB - 1);
        const int ok = j >> 9;               // log2(TPB)

        if (t == ot) {
            float4 bj = bx[ok];
            s_box = bj;
            float a1 = (bj.z - bj.x) * (bj.w - bj.y);
            s_rhs = a1 + 1e-9f;
            g_sel[b * MAXOUT + it] = (val > -5e29f) ? j : -1;
        }
        __syncthreads();

        const float4 bj = s_box;
        const float rhs = s_rhs;

        // ---- suppression fused with next-iteration local argmax ----
        // iou > 0.5  <=>  3*inter > a1 + a2 + eps   (self-iou = 1 auto-suppresses j)
        lv = -3.402823466e38f;
        li = 0;
#pragma unroll
        for (int k = 0; k < KPT; ++k) {
            float4 a = bx[k];
            float tlx = fmaxf(a.x, bj.x);
            float tly = fmaxf(a.y, bj.y);
            float brx = fminf(a.z, bj.z);
            float bry = fminf(a.w, bj.w);
            float w = fmaxf(brx - tlx, 0.f);
            float h = fmaxf(bry - tly, 0.f);
            float inter = w * h;
            float a2 = (a.z - a.x) * (a.w - a.y);
            bool sup = (3.f * inter > rhs + a2);
            float s = sup ? -1e30f : sc[k];
            sc[k] = s;
            if (s > lv) { lv = s; li = t + k * TPB; }
        }
        __syncthreads();
    }
}

// ---------------------------------------------------------------------------
// Kernel 3: gather outputs. Layout: boxes[64*100*4] | labels[64*100] | scores[64*100]
// ---------------------------------------------------------------------------
__global__ void gather_kernel(float* __restrict__ out)
{
    int b = blockIdx.x;
    int s = threadIdx.x;
    if (s >= MAXOUT) return;

    int j = g_sel[b * MAXOUT + s];
    bool valid = (j >= 0);
    int safe = valid ? j : 0;

    float4 bxv = g_boxes[(size_t)b * NANCH + safe];
    float scv  = g_scores[(size_t)b * NANCH + safe];
    int   lbv  = g_labels[(size_t)b * NANCH + safe];

    if (!valid) { bxv = make_float4(0.f, 0.f, 0.f, 0.f); scv = 0.f; }

    reinterpret_cast<float4*>(out)[b * MAXOUT + s] = bxv;
    out[BATCH * MAXOUT * 4 + b * MAXOUT + s] = valid ? (float)lbv : -1.f;
    out[BATCH * MAXOUT * 5 + b * MAXOUT + s] = valid ? scv : 0.f;
}

// ---------------------------------------------------------------------------
extern "C" void kernel_launch(void* const* d_in, const int* in_sizes, int n_in,
                              void* d_out, int out_size)
{
    const float* preds   = (const float*)d_in[0];
    const float* anchors = (const float*)d_in[1];

    decode_kernel<<<(BATCH * NANCH) / 256, 256>>>(preds, anchors);
    nms_kernel<<<BATCH, TPB>>>();
    gather_kernel<<<BATCH, 128>>>((float*)d_out);
}

// round 3
// speedup vs baseline: 1.0453x; 1.0453x over previous
#include <cuda_runtime.h>
#include <cuda_bf16.h>
#include <cstdint>

#define BATCH  64
#define NANCH  8400
#define MAXOUT 100
#define TPB    512
#define KPT    17            // 512*17 = 8704 >= 8400
#define DA     128           // anchors per decode CTA

// ---------------------------------------------------------------------------
// Scratch
// ---------------------------------------------------------------------------
__device__ float4   g_boxes[BATCH * NANCH];
__device__ unsigned g_keys [BATCH * NANCH];   // monotonic score keys (0 = invalid)
__device__ int      g_labels[BATCH * NANCH];

// ---------------------------------------------------------------------------
// Kernel 1: decode with smem-staged coalesced loads.
// CTA = 128 threads <-> 128 anchors. Stage 128*36 float4 into smem (stride 37),
// then each thread processes its own anchor from smem.
// ---------------------------------------------------------------------------
__global__ void __launch_bounds__(DA) decode_kernel(const float* __restrict__ preds,
                                                    const float* __restrict__ anchors)
{
    extern __shared__ float4 sbuf[];          // DA * 37 float4 = 75776 B
    const int t   = threadIdx.x;
    const int cta = blockIdx.x;

    const float4* __restrict__ base =
        reinterpret_cast<const float4*>(preds) + (size_t)cta * DA * 36;

    // ---- coalesced stage: 4608 float4, thread t handles t, t+128, ... ----
#pragma unroll
    for (int u = 0; u < 36; ++u) {
        int i = t + u * DA;
        int a = i / 36;
        int j = i - a * 36;
        sbuf[a * 37 + j] = base[i];
    }
    __syncthreads();

    const float4* mine = sbuf + t * 37;

    // ---- DFL decode ----
    float d[4];
#pragma unroll
    for (int s = 0; s < 4; ++s) {
        float v[16];
#pragma unroll
        for (int q = 0; q < 4; ++q) {
            float4 f = mine[s * 4 + q];
            v[q * 4 + 0] = f.x; v[q * 4 + 1] = f.y;
            v[q * 4 + 2] = f.z; v[q * 4 + 3] = f.w;
        }
        float m = v[0];
#pragma unroll
        for (int i = 1; i < 16; ++i) m = fmaxf(m, v[i]);
        float se = 0.f, ws = 0.f;
#pragma unroll
        for (int i = 0; i < 16; ++i) {
            float e = __expf(v[i] - m);
            se += e;
            ws = fmaf(e, (float)i, ws);
        }
        d[s] = ws / se;
    }

    // ---- class max / argmax (first-max wins) ----
    float best = -3.402823466e38f;
    int lab = 0;
#pragma unroll
    for (int i = 0; i < 20; ++i) {
        float4 f = mine[16 + i];
        if (f.x > best) { best = f.x; lab = 4 * i + 0; }
        if (f.y > best) { best = f.y; lab = 4 * i + 1; }
        if (f.z > best) { best = f.z; lab = 4 * i + 2; }
        if (f.w > best) { best = f.w; lab = 4 * i + 3; }
    }

    // ---- box construction ----
    int gid = cta * DA + t;
    int n = gid % NANCH;
    float4 a = reinterpret_cast<const float4*>(anchors)[n];
    float hw0 = a.z - a.x;
    float hw1 = a.w - a.y;
    float c0 = (a.x + a.z) * 0.5f;
    float c1 = (a.y + a.w) * 0.5f;
    float bc0 = (d[2] - d[0]) * 0.5f * hw0 + c0;
    float bc1 = (d[3] - d[1]) * 0.5f * hw1 + c1;
    float bh0 = (d[2] + d[0]) * hw0;
    float bh1 = (d[3] + d[1]) * hw1;

    float4 box;
    box.x = bc0 - bh0 * 0.5f;
    box.y = bc1 - bh1 * 0.5f;
    box.z = bc0 + bh0 * 0.5f;
    box.w = bc1 + bh1 * 0.5f;

    g_boxes[gid]  = box;
    // monotonic key: scores > 0.3 are positive floats -> fbits + 0x80000000
    g_keys[gid]   = (best > 0.3f) ? (__float_as_uint(best) + 0x80000000u) : 0u;
    g_labels[gid] = lab;
}

// ---------------------------------------------------------------------------
// Kernel 2: greedy NMS, one CTA per image, ONE barrier per iteration.
// Boxes register-resident for suppression + smem-resident for winner fetch.
// Gather fused at the end.
// ---------------------------------------------------------------------------
__global__ void __launch_bounds__(TPB, 1) nms_kernel(float* __restrict__ out)
{
    extern __shared__ float4 s_allbox[];      // 8704 float4 = 139264 B
    __shared__ unsigned long long s_arr[2][16];
    __shared__ int      s_selj[MAXOUT];
    __shared__ unsigned s_selk[MAXOUT];

    const int b    = blockIdx.x;
    const int t    = threadIdx.x;
    const int warp = t >> 5;
    const int lane = t & 31;

    const float4*   __restrict__ gb = g_boxes + (size_t)b * NANCH;
    const unsigned* __restrict__ gk = g_keys  + (size_t)b * NANCH;

    float4   bx[KPT];
    unsigned ky[KPT];
    float    a2[KPT];
    unsigned lk = 0u;
    int      li = 0;

#pragma unroll
    for (int k = 0; k < KPT; ++k) {
        int idx = t + k * TPB;
        float4 v = make_float4(0.f, 0.f, 0.f, 0.f);
        unsigned kk = 0u;
        if (idx < NANCH) { v = gb[idx]; kk = gk[idx]; }
        bx[k] = v;
        ky[k] = kk;
        a2[k] = (v.z - v.x) * (v.w - v.y);
        s_allbox[idx] = v;
        if (kk > lk) { lk = kk; li = idx; }      // ascending k -> lowest idx on tie
    }
    __syncthreads();

    for (int it = 0; it < MAXOUT; ++it) {
        const int p = it & 1;

        // ---- warp reduction: max key, min index on tie ----
        unsigned wm   = __reduce_max_sync(0xffffffffu, lk);
        unsigned cand = (lk == wm) ? (unsigned)li : 0xffffffffu;
        unsigned lim  = __reduce_min_sync(0xffffffffu, cand);
        if (lane == 0)
            s_arr[p][warp] = ((unsigned long long)wm << 32) | (unsigned)(65535u - lim);

        __syncthreads();     // the ONLY barrier in the iteration

        // ---- every thread scans the 16 warp results ----
        unsigned long long bestp = s_arr[p][0];
#pragma unroll
        for (int w = 1; w < 16; ++w) {
            unsigned long long e = s_arr[p][w];
            if (e > bestp) bestp = e;
        }
        unsigned wkey = (unsigned)(bestp >> 32);
        int j = 65535 - (int)(bestp & 0xffffffffu);

        if (t == 0) { s_selj[it] = j; s_selk[it] = wkey; }

        float4 bj = s_allbox[j];                       // broadcast LDS
        float rhs = (bj.z - bj.x) * (bj.w - bj.y) + 1e-9f;

        // ---- suppression fused with next local argmax ----
        // iou > 0.5  <=>  3*inter > a1 + a2 + eps  (self-iou = 1 kills j)
        lk = 0u; li = 0;
#pragma unroll
        for (int k = 0; k < KPT; ++k) {
            float4 a = bx[k];
            float tlx = fmaxf(a.x, bj.x);
            float tly = fmaxf(a.y, bj.y);
            float brx = fminf(a.z, bj.z);
            float bry = fminf(a.w, bj.w);
            float w = fmaxf(brx - tlx, 0.f);
            float h = fmaxf(bry - tly, 0.f);
            float inter = w * h;
            bool sup = (3.f * inter > rhs + a2[k]);
            unsigned kk = sup ? 0u : ky[k];
            ky[k] = kk;
            if (kk > lk) { lk = kk; li = t + k * TPB; }
        }
    }

    __syncthreads();

    // ---- fused gather: boxes | labels | scores ----
    if (t < MAXOUT) {
        int j = s_selj[t];
        unsigned key = s_selk[t];
        bool valid = (key != 0u);

        float4 bv = s_allbox[j];
        float  sv = __uint_as_float(key - 0x80000000u);
        int    lb = valid ? g_labels[(size_t)b * NANCH + j] : -1;
        if (!valid) { bv = make_float4(0.f, 0.f, 0.f, 0.f); sv = 0.f; }

        reinterpret_cast<float4*>(out)[b * MAXOUT + t] = bv;
        out[BATCH * MAXOUT * 4 + b * MAXOUT + t] = valid ? (float)lb : -1.f;
        out[BATCH * MAXOUT * 5 + b * MAXOUT + t] = sv;
    }
}

// ---------------------------------------------------------------------------
extern "C" void kernel_launch(void* const* d_in, const int* in_sizes, int n_in,
                              void* d_out, int out_size)
{
    const float* preds   = (const float*)d_in[0];
    const float* anchors = (const float*)d_in[1];

    static int attr_done = 0;
    if (!attr_done) {
        cudaFuncSetAttribute(decode_kernel,
                             cudaFuncAttributeMaxDynamicSharedMemorySize, DA * 37 * 16);
        cudaFuncSetAttribute(nms_kernel,
                             cudaFuncAttributeMaxDynamicSharedMemorySize, 8704 * 16);
        attr_done = 1;
    }

    decode_kernel<<<(BATCH * NANCH) / DA, DA, DA * 37 * 16>>>(preds, anchors);
    nms_kernel<<<BATCH, TPB, 8704 * 16>>>((float*)d_out);
}

// round 4
// speedup vs baseline: 1.0979x; 1.0503x over previous
#include <cuda_runtime.h>
#include <cuda_bf16.h>
#include <cstdint>

#define BATCH  64
#define NANCH  8400
#define HALF   4200
#define MAXOUT 100
#define TPB    512
#define KPT    9             // 512*9 = 4608 >= 4200
#define DT     256           // decode threads per CTA
#define DAANCH 128           // anchors per decode CTA (2 threads/anchor)

// ---------------------------------------------------------------------------
// Scratch
// ---------------------------------------------------------------------------
__device__ float4   g_boxes[BATCH * NANCH];
__device__ unsigned g_keys [BATCH * NANCH];   // monotonic score keys (0 = invalid)
__device__ int      g_labels[BATCH * NANCH];

// ---------------------------------------------------------------------------
// Kernel 1: decode. 256 threads stage 128 anchors (coalesced), then
// 2 threads per anchor: half h computes DFL sides {h, h+2} and classes
// [h*40, h*40+40), merged via shfl_xor(1).
// ---------------------------------------------------------------------------
__global__ void __launch_bounds__(DT) decode_kernel(const float* __restrict__ preds,
                                                    const float* __restrict__ anchors)
{
    extern __shared__ float4 sbuf[];          // 128 * 37 float4 = 75776 B
    const int t   = threadIdx.x;
    const int cta = blockIdx.x;

    const float4* __restrict__ base =
        reinterpret_cast<const float4*>(preds) + (size_t)cta * DAANCH * 36;

    // ---- coalesced stage: 4608 float4, incremental div by 36 ----
    {
        int a = t / 36;
        int j = t - a * 36;
#pragma unroll
        for (int u = 0; u < 18; ++u) {
            sbuf[a * 37 + j] = base[t + u * DT];
            a += 7; j += 4;                    // += 256 = 7*36 + 4
            if (j >= 36) { j -= 36; ++a; }
        }
    }
    __syncthreads();

    const int an = t >> 1;                     // anchor within CTA
    const int h  = t & 1;                      // half: 0 or 1
    const float4* mine = sbuf + an * 37;

    // ---- DFL: sides h and h+2 (identical per-side arithmetic) ----
    float ds[2];
#pragma unroll
    for (int si = 0; si < 2; ++si) {
        const int s = h + si * 2;
        float v[16];
#pragma unroll
        for (int q = 0; q < 4; ++q) {
            float4 f = mine[s * 4 + q];
            v[q * 4 + 0] = f.x; v[q * 4 + 1] = f.y;
            v[q * 4 + 2] = f.z; v[q * 4 + 3] = f.w;
        }
        float m = v[0];
#pragma unroll
        for (int i = 1; i < 16; ++i) m = fmaxf(m, v[i]);
        float se = 0.f, ws = 0.f;
#pragma unroll
        for (int i = 0; i < 16; ++i) {
            float e = __expf(v[i] - m);
            se += e;
            ws = fmaf(e, (float)i, ws);
        }
        ds[si] = ws / se;
    }

    // ---- classes: half h scans classes [40h, 40h+40), sequential order ----
    float best = -3.402823466e38f;
    int lab = 0;
#pragma unroll
    for (int i = 0; i < 10; ++i) {
        float4 f = mine[16 + h * 10 + i];
        int c = h * 40 + 4 * i;
        if (f.x > best) { best = f.x; lab = c + 0; }
        if (f.y > best) { best = f.y; lab = c + 1; }
        if (f.z > best) { best = f.z; lab = c + 2; }
        if (f.w > best) { best = f.w; lab = c + 3; }
    }

    // ---- per-half box coords (even: x/z from d0,d2; odd: y/w from d1,d3) ----
    const int gid = cta * DAANCH + an;
    const int nn  = gid % NANCH;
    float4 av = reinterpret_cast<const float4*>(anchors)[nn];
    float aa = h ? av.y : av.x;
    float ab = h ? av.w : av.z;
    float hw = ab - aa;
    float c0 = (aa + ab) * 0.5f;
    float bc = (ds[1] - ds[0]) * 0.5f * hw + c0;
    float bh = (ds[1] + ds[0]) * hw;
    float lo = bc - bh * 0.5f;
    float hi = bc + bh * 0.5f;

    // ---- merge with partner ----
    float olo = __shfl_xor_sync(0xffffffffu, lo, 1);
    float ohi = __shfl_xor_sync(0xffffffffu, hi, 1);
    float ob  = __shfl_xor_sync(0xffffffffu, best, 1);
    int   ol  = __shfl_xor_sync(0xffffffffu, lab, 1);

    // lowest class index wins ties (half0 indices < half1 indices)
    if (ob > best || (ob == best && ol < lab)) { best = ob; lab = ol; }

    if (h == 0) {
        float4 box;
        box.x = lo;  box.y = olo;  box.z = hi;  box.w = ohi;
        g_boxes[gid] = box;
    } else {
        g_keys[gid]   = (best > 0.3f) ? (__float_as_uint(best) + 0x80000000u) : 0u;
        g_labels[gid] = lab;
    }
}

// ---------------------------------------------------------------------------
// mbarrier helpers (cluster-scope acquire wait)
// ---------------------------------------------------------------------------
__device__ __forceinline__ void mbar_wait_cluster(uint32_t mbar, unsigned parity)
{
    unsigned done;
    asm volatile(
        "{\n\t.reg .pred p;\n\t"
        "mbarrier.try_wait.parity.acquire.cluster.shared::cta.b64 p, [%1], %2;\n\t"
        "selp.b32 %0, 1, 0, p;\n\t}"
        : "=r"(done) : "r"(mbar), "r"(parity) : "memory");
    if (!done) {
        asm volatile(
            "{\n\t.reg .pred P1;\n\t"
            "WL_%=:\n\t"
            "mbarrier.try_wait.parity.acquire.cluster.shared::cta.b64 P1, [%0], %1, 0x989680;\n\t"
            "@P1 bra.uni WD_%=;\n\t"
            "bra.uni WL_%=;\n\t"
            "WD_%=:\n\t}"
            :: "r"(mbar), "r"(parity) : "memory");
    }
}

// ---------------------------------------------------------------------------
// Kernel 2: greedy NMS, 2-CTA cluster per image. Each CTA suppresses half the
// boxes (register-resident); winners exchanged per-iteration via DSMEM.
// Full box table smem-resident in both CTAs. Gather fused (rank 0).
// ---------------------------------------------------------------------------
__global__ void __launch_bounds__(TPB, 1) __cluster_dims__(2, 1, 1)
nms_kernel(float* __restrict__ out)
{
    extern __shared__ float4 s_allbox[];      // 8400 float4 = 134400 B
    __shared__ unsigned long long s_arr[16];
    __shared__ unsigned long long s_mail[2];
    __shared__ unsigned long long s_mbar;
    __shared__ int      s_selj[MAXOUT];
    __shared__ unsigned s_selk[MAXOUT];

    const int rank = blockIdx.x & 1;
    const int peer = rank ^ 1;
    const int b    = blockIdx.x >> 1;
    const int t    = threadIdx.x;
    const int warp = t >> 5;
    const int lane = t & 31;

    const uint32_t mbar_a = (uint32_t)__cvta_generic_to_shared(&s_mbar);
    const uint32_t mail_a = (uint32_t)__cvta_generic_to_shared(&s_mail[0]);

    const float4*   __restrict__ gb = g_boxes + (size_t)b * NANCH;
    const unsigned* __restrict__ gk = g_keys  + (size_t)b * NANCH;

    if (t == 0) {
        asm volatile("mbarrier.init.shared.b64 [%0], 1;" :: "r"(mbar_a) : "memory");
    }

    // full box table (both CTAs)
    for (int i = t; i < NANCH; i += TPB) s_allbox[i] = gb[i];

    // this CTA's half, register-resident
    float4   bx[KPT];
    unsigned ky[KPT];
    float    a2[KPT];
    unsigned lk = 0u;
    int      li = 0;
    const int baseg = rank * HALF + t;

#pragma unroll
    for (int k = 0; k < KPT; ++k) {
        int loc = t + k * TPB;
        float4 v = make_float4(0.f, 0.f, 0.f, 0.f);
        unsigned kk = 0u;
        int gidx = baseg + k * TPB;
        if (loc < HALF) { v = gb[gidx]; kk = gk[gidx]; }
        bx[k] = v;
        ky[k] = kk;
        a2[k] = (v.z - v.x) * (v.w - v.y);
        if (kk > lk) { lk = kk; li = gidx; }   // ascending k -> lowest idx on tie
    }
    __syncthreads();

    // cluster barrier: peer's mbarrier init + smem ready before first exchange
    asm volatile("barrier.cluster.arrive.aligned;" ::: "memory");
    asm volatile("barrier.cluster.wait.aligned;" ::: "memory");

    for (int it = 0; it < MAXOUT; ++it) {
        const unsigned par = it & 1u;

        // ---- warp reduction: max key, min global index on tie ----
        unsigned wm   = __reduce_max_sync(0xffffffffu, lk);
        unsigned cand = (lk == wm) ? (unsigned)li : 0xffffffffu;
        unsigned lim  = __reduce_min_sync(0xffffffffu, cand);
        if (lane == 0)
            s_arr[warp] = ((unsigned long long)wm << 32) | (unsigned)(65535u - lim);

        __syncthreads();

        // ---- CTA winner: every thread scans the 16 warp results ----
        unsigned long long locw = s_arr[0];
#pragma unroll
        for (int w = 1; w < 16; ++w) {
            unsigned long long e = s_arr[w];
            if (e > locw) locw = e;
        }

        // ---- cross-CTA exchange via DSMEM ----
        if (t == 0) {
            uint32_t rmail, rbar;
            asm volatile("mapa.shared::cluster.u32 %0, %1, %2;"
                         : "=r"(rmail) : "r"(mail_a + par * 8u), "r"(peer));
            asm volatile("st.shared::cluster.u64 [%0], %1;"
                         :: "r"(rmail), "l"(locw) : "memory");
            asm volatile("mapa.shared::cluster.u32 %0, %1, %2;"
                         : "=r"(rbar) : "r"(mbar_a), "r"(peer));
            asm volatile("mbarrier.arrive.release.cluster.shared::cluster.b64 _, [%0];"
                         :: "r"(rbar) : "memory");
        }
        mbar_wait_cluster(mbar_a, par);

        unsigned long long pw = s_mail[par];
        unsigned long long comb = (pw > locw) ? pw : locw;
        unsigned wkey = (unsigned)(comb >> 32);
        int j = 65535 - (int)(comb & 0xffffffffu);

        if (t == 0) { s_selj[it] = j; s_selk[it] = wkey; }

        float4 bj = s_allbox[j];                       // broadcast LDS
        float rhs = (bj.z - bj.x) * (bj.w - bj.y) + 1e-9f;

        // ---- suppression fused with next local argmax ----
        // iou > 0.5  <=>  3*inter > a1 + a2 + eps  (self-iou = 1 kills j)
        lk = 0u; li = 0;
#pragma unroll
        for (int k = 0; k < KPT; ++k) {
            float4 a = bx[k];
            float tlx = fmaxf(a.x, bj.x);
            float tly = fmaxf(a.y, bj.y);
            float brx = fminf(a.z, bj.z);
            float bry = fminf(a.w, bj.w);
            float w = fmaxf(brx - tlx, 0.f);
            float hh = fmaxf(bry - tly, 0.f);
            float inter = w * hh;
            bool sup = (3.f * inter > rhs + a2[k]);
            unsigned kk = sup ? 0u : ky[k];
            ky[k] = kk;
            if (kk > lk) { lk = kk; li = baseg + k * TPB; }
        }
    }

    __syncthreads();

    // ---- fused gather (rank 0): boxes | labels | scores ----
    if (rank == 0 && t < MAXOUT) {
        int j = s_selj[t];
        unsigned key = s_selk[t];
        bool valid = (key != 0u);

        float4 bv = s_allbox[j];
        float  sv = __uint_as_float(key - 0x80000000u);
        int    lb = valid ? g_labels[(size_t)b * NANCH + j] : -1;
        if (!valid) { bv = make_float4(0.f, 0.f, 0.f, 0.f); sv = 0.f; }

        reinterpret_cast<float4*>(out)[b * MAXOUT + t] = bv;
        out[BATCH * MAXOUT * 4 + b * MAXOUT + t] = valid ? (float)lb : -1.f;
        out[BATCH * MAXOUT * 5 + b * MAXOUT + t] = sv;
    }

    // no CTA may exit while its peer might still arrive on this CTA's mbar
    asm volatile("barrier.cluster.arrive.aligned;" ::: "memory");
    asm volatile("barrier.cluster.wait.aligned;" ::: "memory");
}

// ---------------------------------------------------------------------------
extern "C" void kernel_launch(void* const* d_in, const int* in_sizes, int n_in,
                              void* d_out, int out_size)
{
    const float* preds   = (const float*)d_in[0];
    const float* anchors = (const float*)d_in[1];

    static int attr_done = 0;
    if (!attr_done) {
        cudaFuncSetAttribute(decode_kernel,
                             cudaFuncAttributeMaxDynamicSharedMemorySize, DAANCH * 37 * 16);
        cudaFuncSetAttribute(nms_kernel,
                             cudaFuncAttributeMaxDynamicSharedMemorySize, NANCH * 16);
        attr_done = 1;
    }

    decode_kernel<<<(BATCH * NANCH) / DAANCH, DT, DAANCH * 37 * 16>>>(preds, anchors);
    nms_kernel<<<BATCH * 2, TPB, NANCH * 16>>>((float*)d_out);
}